// round 15
// baseline (speedup 1.0000x reference)
#include <cuda_runtime.h>

#define BATCH   64
#define NTOK    4096
#define CH      1024
#define KANCH   8
#define NSPLIT  16
#define TOK_PER (NTOK / NSPLIT)   // 256
#define C4      (CH / 4)          // 256 float4 per row

// Scratch (device globals — no allocation allowed).
// __align__(16): accessed through float4* (R11/R12 trapped without it).
__device__ __align__(16) float g_partial[NSPLIT * BATCH * CH];  // 4 MB
__device__ __align__(16) float g_desc[BATCH * CH];              // normalized descriptors
__device__ int      g_ids[BATCH];
__device__ unsigned g_cnt[BATCH];   // per-batch arrival counters
// Counters are monotone: (old % 16 == 15) detects the last arrival of THIS
// replay, so no reset is needed and the kernels stay graph-replayable.

// ---------------------------------------------------------------------------
// Fused kernel: streaming partial sums (HBM-bound, 1 GiB) + per-batch
// combiner. The 16th block to finish a batch combines its partials, computes
// the normalized descriptor, cosine sims and argmax — overlapped with the
// rest of the streaming work. ~145-158us at ~86% DRAM (practical ceiling).
// ---------------------------------------------------------------------------
__global__ __launch_bounds__(256, 8) void k_main(const float* __restrict__ x,
                                                 const float* __restrict__ anchors,
                                                 float* __restrict__ out) {
    const int ns = blockIdx.x;
    const int b  = blockIdx.y;
    const int t  = threadIdx.x;  // 0..255 -> channels 4t..4t+3

    // ---- streaming phase (__ldcs: read-once data, evict-first) ----
    {
        const float4* p = reinterpret_cast<const float4*>(x)
                        + (size_t)b * NTOK * C4
                        + (size_t)ns * TOK_PER * C4
                        + t;
        float4 acc = make_float4(0.f, 0.f, 0.f, 0.f);
#pragma unroll 8
        for (int n = 0; n < TOK_PER; ++n) {
            float4 v = __ldcs(p);
            p += C4;
            acc.x += v.x; acc.y += v.y; acc.z += v.z; acc.w += v.w;
        }
        reinterpret_cast<float4*>(g_partial)[(size_t)(ns * BATCH + b) * C4 + t] = acc;
    }

    __threadfence();
    __syncthreads();
    __shared__ unsigned s_old;
    if (t == 0) s_old = atomicAdd(&g_cnt[b], 1u);
    __syncthreads();
    if ((s_old & 15u) != 15u) return;   // not the last arrival for this batch

    __threadfence();   // acquire: order peers' partial stores before our loads

    // ---- combiner phase (one block per batch, 63/64 overlapped) ----
    const int lane = t & 31;
    const int w    = t >> 5;

    float4 s = make_float4(0.f, 0.f, 0.f, 0.f);
#pragma unroll
    for (int nsi = 0; nsi < NSPLIT; ++nsi) {
        float4 v = __ldcg(reinterpret_cast<const float4*>(g_partial)
                          + (size_t)(nsi * BATCH + b) * C4 + t);
        s.x += v.x; s.y += v.y; s.z += v.z; s.w += v.w;
    }
    const float inv_n = 1.0f / (float)NTOK;
    s.x *= inv_n; s.y *= inv_n; s.z *= inv_n; s.w *= inv_n;

    __shared__ float warp_s[8];
    __shared__ float s_invnorm;
    float ss = s.x * s.x + s.y * s.y + s.z * s.z + s.w * s.w;
#pragma unroll
    for (int off = 16; off > 0; off >>= 1)
        ss += __shfl_xor_sync(0xffffffffu, ss, off);
    if (lane == 0) warp_s[w] = ss;
    __syncthreads();
    if (t == 0) {
        float tot = 0.f;
#pragma unroll
        for (int i = 0; i < 8; ++i) tot += warp_s[i];
        s_invnorm = 1.0f / fmaxf(sqrtf(tot), 1e-12f);
    }
    __syncthreads();

    const float invn = s_invnorm;
    float4 d = make_float4(s.x * invn, s.y * invn, s.z * invn, s.w * invn);
    reinterpret_cast<float4*>(g_desc)[(size_t)b * C4 + t] = d;

    float dot[KANCH];
#pragma unroll
    for (int k = 0; k < KANCH; ++k) {
        float4 a = __ldg(reinterpret_cast<const float4*>(anchors) + (size_t)k * C4 + t);
        dot[k] = d.x * a.x + d.y * a.y + d.z * a.z + d.w * a.w;
    }
#pragma unroll
    for (int off = 16; off > 0; off >>= 1) {
#pragma unroll
        for (int k = 0; k < KANCH; ++k)
            dot[k] += __shfl_xor_sync(0xffffffffu, dot[k], off);
    }
    __shared__ float wd[8][KANCH];
    if (lane == 0) {
#pragma unroll
        for (int k = 0; k < KANCH; ++k) wd[w][k] = dot[k];
    }
    __syncthreads();
    if (t == 0) {
        float simk[KANCH];
#pragma unroll
        for (int k = 0; k < KANCH; ++k) {
            float acc = 0.f;
#pragma unroll
            for (int i = 0; i < 8; ++i) acc += wd[i][k];
            simk[k] = acc;
        }
        // argmin(1 - sim) == first max of sim (strict > keeps first occurrence)
        int   best   = 0;
        float best_s = simk[0];
#pragma unroll
        for (int k = 1; k < KANCH; ++k)
            if (simk[k] > best_s) { best_s = simk[k]; best = k; }
        g_ids[b] = best;
        out[b]   = (float)best;
    }
}

// ---------------------------------------------------------------------------
// k_ema3: 2-warps-per-anchor EMA (8 independent chains; in-chain batch order
// preserved => equivalent to the sequential scan).
// R14 post-mortem: d[8]+temps hit the 64-reg ceiling and ptxas serialized
// the descriptor loads (MLP 1 -> ~16us). Splitting each anchor across 2
// warps halves the footprint: state A[4] (16 regs) + prefetch d[4] (16 regs)
// ~= 45 regs -> loads batch, state stays in registers.
// Per-step: one fused update pass (scalar-scale trick: a_true = scale*raw),
// intra-warp shfl reduce, cross-warp exchange via parity-buffered smem +
// named barrier (64 threads), rsqrtf. |v|^2 in [0.64,1.21] -> eps never binds.
// ---------------------------------------------------------------------------
__global__ __launch_bounds__(512) void k_ema3(const float* __restrict__ anchors,
                                              const float* __restrict__ counts,
                                              float* __restrict__ out) {
    __shared__ int   s_list[KANCH][BATCH];
    __shared__ int   s_len[KANCH];
    __shared__ float wpart[2][KANCH][2];   // [parity][anchor][warp-half]

    const int t    = threadIdx.x;   // 0..511
    const int lane = t & 31;
    const int p    = (t >> 5) & 1;  // which half of the anchor
    const int g    = t >> 6;        // anchor id, 0..7

    // Build per-anchor sample lists (order preserved).
    if (t < KANCH) {
        int n = 0;
        for (int b = 0; b < BATCH; ++b)
            if (g_ids[b] == t) s_list[t][n++] = b;
        s_len[t] = n;
    }
    __syncthreads();

    const int len = s_len[g];

    // Thread owns C4-indices {j*64 + p*32 + lane : j in 0..3} of anchor g.
    float4 A[4];
#pragma unroll
    for (int j = 0; j < 4; ++j)
        A[j] = __ldg(reinterpret_cast<const float4*>(anchors)
                     + (size_t)g * C4 + j * 64 + p * 32 + lane);
    float c     = __ldg(counts + g);
    float scale = 1.0f;             // a_true = scale * A

    // Prefetch first sample's descriptor slice (4 batched LDG.128).
    float4 d[4];
    if (len > 0) {
        const int b0 = s_list[g][0];
#pragma unroll
        for (int j = 0; j < 4; ++j)
            d[j] = __ldg(reinterpret_cast<const float4*>(g_desc)
                         + (size_t)b0 * C4 + j * 64 + p * 32 + lane);
    }

    for (int i = 0; i < len; ++i) {
        const float m  = (c < 1.0f) ? 0.0f : 0.9f;
        const float im = 1.0f - m;
        const float ma = m * scale;

        float s0 = 0.f, s1 = 0.f, s2 = 0.f, s3 = 0.f;
#pragma unroll
        for (int j = 0; j < 4; ++j) {
            A[j].x = ma * A[j].x + im * d[j].x;
            A[j].y = ma * A[j].y + im * d[j].y;
            A[j].z = ma * A[j].z + im * d[j].z;
            A[j].w = ma * A[j].w + im * d[j].w;
            s0 += A[j].x * A[j].x; s1 += A[j].y * A[j].y;
            s2 += A[j].z * A[j].z; s3 += A[j].w * A[j].w;
        }

        // Prefetch next sample's slice; overlaps the reduce + barrier below.
        if (i + 1 < len) {
            const int bn = s_list[g][i + 1];
#pragma unroll
            for (int j = 0; j < 4; ++j)
                d[j] = __ldg(reinterpret_cast<const float4*>(g_desc)
                             + (size_t)bn * C4 + j * 64 + p * 32 + lane);
        }

        float ssum = (s0 + s1) + (s2 + s3);
#pragma unroll
        for (int off = 16; off > 0; off >>= 1)
            ssum += __shfl_xor_sync(0xffffffffu, ssum, off);
        if (lane == 0) wpart[i & 1][g][p] = ssum;

        asm volatile("bar.sync %0, 64;" :: "r"(g + 1) : "memory");

        const float tot = wpart[i & 1][g][0] + wpart[i & 1][g][1];
        scale = rsqrtf(tot);        // |v| in [0.8, 1.1]; eps guard never binds
        c += 1.0f;
        // wpart slot (i&1) is rewritten at step i+2, after the barrier at
        // step i+1 -> no WAR hazard.
    }

    // Emit new_anchors (scale applied) then new_counts.
#pragma unroll
    for (int j = 0; j < 4; ++j) {
        float4 v = A[j];
        v.x *= scale; v.y *= scale; v.z *= scale; v.w *= scale;
        reinterpret_cast<float4*>(out + BATCH)[(size_t)g * C4 + j * 64 + p * 32 + lane] = v;
    }
    if ((t & 63) == 0) out[BATCH + KANCH * CH + g] = c;
}

// ---------------------------------------------------------------------------
extern "C" void kernel_launch(void* const* d_in, const int* in_sizes, int n_in,
                              void* d_out, int out_size) {
    const float* prompt_tokens = (const float*)d_in[0];  // [64,4096,1024] f32
    const float* anchors       = (const float*)d_in[1];  // [8,1024] f32
    const float* counts        = (const float*)d_in[2];  // [8] f32
    float* out = (float*)d_out;  // [64 ids | 8192 anchors | 8 counts] f32

    dim3 grid1(NSPLIT, BATCH);
    k_main<<<grid1, 256>>>(prompt_tokens, anchors, out);
    k_ema3<<<1, 512>>>(anchors, counts, out);
}

// round 16
// speedup vs baseline: 1.0109x; 1.0109x over previous
#include <cuda_runtime.h>

#define BATCH   64
#define NTOK    4096
#define CH      1024
#define KANCH   8
#define NSPLIT  16
#define TOK_PER (NTOK / NSPLIT)   // 256
#define C4      (CH / 4)          // 256 float4 per row

// Scratch (device globals — no allocation allowed).
// __align__(16): accessed through float4* (R11/R12 trapped without it).
__device__ __align__(16) float g_partial[NSPLIT * BATCH * CH];  // 4 MB
__device__ __align__(16) float g_desc[BATCH * CH];              // normalized descriptors
__device__ int      g_ids[BATCH];
__device__ unsigned g_cnt[BATCH];   // per-batch arrival counters
// Counters are monotone: (old % 16 == 15) detects the last arrival of THIS
// replay, so no reset is needed and the kernels stay graph-replayable.

// ---------------------------------------------------------------------------
// Fused kernel: streaming partial sums (HBM-bound, 1 GiB) + per-batch
// combiner. The 16th block to finish a batch combines its partials, computes
// the normalized descriptor, cosine sims and argmax — overlapped with the
// rest of the streaming work. ~145-158us at ~86% DRAM (practical ceiling).
// ---------------------------------------------------------------------------
__global__ __launch_bounds__(256, 8) void k_main(const float* __restrict__ x,
                                                 const float* __restrict__ anchors,
                                                 float* __restrict__ out) {
    const int ns = blockIdx.x;
    const int b  = blockIdx.y;
    const int t  = threadIdx.x;  // 0..255 -> channels 4t..4t+3

    // ---- streaming phase (__ldcs: read-once data, evict-first) ----
    {
        const float4* p = reinterpret_cast<const float4*>(x)
                        + (size_t)b * NTOK * C4
                        + (size_t)ns * TOK_PER * C4
                        + t;
        float4 acc = make_float4(0.f, 0.f, 0.f, 0.f);
#pragma unroll 8
        for (int n = 0; n < TOK_PER; ++n) {
            float4 v = __ldcs(p);
            p += C4;
            acc.x += v.x; acc.y += v.y; acc.z += v.z; acc.w += v.w;
        }
        reinterpret_cast<float4*>(g_partial)[(size_t)(ns * BATCH + b) * C4 + t] = acc;
    }

    __threadfence();
    __syncthreads();
    __shared__ unsigned s_old;
    if (t == 0) s_old = atomicAdd(&g_cnt[b], 1u);
    __syncthreads();
    if ((s_old & 15u) != 15u) return;   // not the last arrival for this batch

    __threadfence();   // acquire: order peers' partial stores before our loads

    // ---- combiner phase (one block per batch, 63/64 overlapped) ----
    const int lane = t & 31;
    const int w    = t >> 5;

    float4 s = make_float4(0.f, 0.f, 0.f, 0.f);
#pragma unroll
    for (int nsi = 0; nsi < NSPLIT; ++nsi) {
        float4 v = __ldcg(reinterpret_cast<const float4*>(g_partial)
                          + (size_t)(nsi * BATCH + b) * C4 + t);
        s.x += v.x; s.y += v.y; s.z += v.z; s.w += v.w;
    }
    const float inv_n = 1.0f / (float)NTOK;
    s.x *= inv_n; s.y *= inv_n; s.z *= inv_n; s.w *= inv_n;

    __shared__ float warp_s[8];
    __shared__ float s_invnorm;
    float ss = s.x * s.x + s.y * s.y + s.z * s.z + s.w * s.w;
#pragma unroll
    for (int off = 16; off > 0; off >>= 1)
        ss += __shfl_xor_sync(0xffffffffu, ss, off);
    if (lane == 0) warp_s[w] = ss;
    __syncthreads();
    if (t == 0) {
        float tot = 0.f;
#pragma unroll
        for (int i = 0; i < 8; ++i) tot += warp_s[i];
        s_invnorm = 1.0f / fmaxf(sqrtf(tot), 1e-12f);
    }
    __syncthreads();

    const float invn = s_invnorm;
    float4 d = make_float4(s.x * invn, s.y * invn, s.z * invn, s.w * invn);
    reinterpret_cast<float4*>(g_desc)[(size_t)b * C4 + t] = d;

    float dot[KANCH];
#pragma unroll
    for (int k = 0; k < KANCH; ++k) {
        float4 a = __ldg(reinterpret_cast<const float4*>(anchors) + (size_t)k * C4 + t);
        dot[k] = d.x * a.x + d.y * a.y + d.z * a.z + d.w * a.w;
    }
#pragma unroll
    for (int off = 16; off > 0; off >>= 1) {
#pragma unroll
        for (int k = 0; k < KANCH; ++k)
            dot[k] += __shfl_xor_sync(0xffffffffu, dot[k], off);
    }
    __shared__ float wd[8][KANCH];
    if (lane == 0) {
#pragma unroll
        for (int k = 0; k < KANCH; ++k) wd[w][k] = dot[k];
    }
    __syncthreads();
    if (t == 0) {
        float simk[KANCH];
#pragma unroll
        for (int k = 0; k < KANCH; ++k) {
            float acc = 0.f;
#pragma unroll
            for (int i = 0; i < 8; ++i) acc += wd[i][k];
            simk[k] = acc;
        }
        // argmin(1 - sim) == first max of sim (strict > keeps first occurrence)
        int   best   = 0;
        float best_s = simk[0];
#pragma unroll
        for (int k = 1; k < KANCH; ++k)
            if (simk[k] > best_s) { best_s = simk[k]; best = k; }
        g_ids[b] = best;
        out[b]   = (float)best;
    }
}

// ---------------------------------------------------------------------------
// k_ema4: 4-warps-per-anchor EMA (8 independent chains; in-chain batch order
// preserved => equivalent to the sequential scan).
// Evolution: R14 (1 warp/anchor) hit the 64-reg ceiling -> MLP 1, 15.9us.
// R15 (2 warps/anchor) regs=53, 11.9us — loads still only partly hidden.
// R16: 4 warps/anchor -> per thread 8 channels: A[2]+d[2] = 16 regs of state;
// the 2-load wave per step is fully covered by the reduce+barrier, and the
// chain-list index comes from a register via shfl (no LDS on that path).
// Scalar-scale trick kept: a_true = scale*raw, one fused pass per step;
// |v|^2 in [0.64,1.21] so rsqrtf's guard-free form is safe.
// ---------------------------------------------------------------------------
__global__ __launch_bounds__(1024) void k_ema4(const float* __restrict__ anchors,
                                               const float* __restrict__ counts,
                                               float* __restrict__ out) {
    __shared__ int   s_list[KANCH][BATCH];
    __shared__ int   s_len[KANCH];
    __shared__ float wpart[2][KANCH][4];   // [parity][anchor][quarter]

    const int t    = threadIdx.x;   // 0..1023
    const int lane = t & 31;
    const int q    = (t >> 5) & 3;  // quarter of the anchor, 0..3
    const int g    = t >> 7;        // anchor id, 0..7

    // Build per-anchor sample lists (order preserved).
    if (t < KANCH) {
        int n = 0;
        for (int b = 0; b < BATCH; ++b)
            if (g_ids[b] == t) s_list[t][n++] = b;
        s_len[t] = n;
    }
    __syncthreads();

    const int len = s_len[g];
    // Lane l caches list entries l and 32+l; broadcast per step via shfl_idx.
    int myl0 = s_list[g][lane];
    int myl1 = s_list[g][32 + lane];

    // Thread owns C4-indices {j*128 + q*32 + lane : j in 0..1} of anchor g.
    const int base = q * 32 + lane;
    float4 A[2];
#pragma unroll
    for (int j = 0; j < 2; ++j)
        A[j] = __ldg(reinterpret_cast<const float4*>(anchors)
                     + (size_t)g * C4 + j * 128 + base);
    float c     = __ldg(counts + g);
    float scale = 1.0f;             // a_true = scale * A

    // Prefetch first sample's slice (2 batched LDG.128).
    float4 d[2];
    if (len > 0) {
        const int b0 = __shfl_sync(0xffffffffu, myl0, 0);
#pragma unroll
        for (int j = 0; j < 2; ++j)
            d[j] = __ldg(reinterpret_cast<const float4*>(g_desc)
                         + (size_t)b0 * C4 + j * 128 + base);
    }

    for (int i = 0; i < len; ++i) {
        const float m  = (c < 1.0f) ? 0.0f : 0.9f;
        const float im = 1.0f - m;
        const float ma = m * scale;

        float s0 = 0.f, s1 = 0.f;
#pragma unroll
        for (int j = 0; j < 2; ++j) {
            A[j].x = ma * A[j].x + im * d[j].x;
            A[j].y = ma * A[j].y + im * d[j].y;
            A[j].z = ma * A[j].z + im * d[j].z;
            A[j].w = ma * A[j].w + im * d[j].w;
            s0 += A[j].x * A[j].x + A[j].z * A[j].z;
            s1 += A[j].y * A[j].y + A[j].w * A[j].w;
        }

        // Prefetch next sample's slice; overlaps the reduce + barrier below.
        if (i + 1 < len) {
            const int nxt = i + 1;
            const int bn  = __shfl_sync(0xffffffffu,
                                        (nxt < 32) ? myl0 : myl1, nxt & 31);
#pragma unroll
            for (int j = 0; j < 2; ++j)
                d[j] = __ldg(reinterpret_cast<const float4*>(g_desc)
                             + (size_t)bn * C4 + j * 128 + base);
        }

        float ssum = s0 + s1;
#pragma unroll
        for (int off = 16; off > 0; off >>= 1)
            ssum += __shfl_xor_sync(0xffffffffu, ssum, off);
        if (lane == 0) wpart[i & 1][g][q] = ssum;

        asm volatile("bar.sync %0, 128;" :: "r"(g + 1) : "memory");

        const float tot = (wpart[i & 1][g][0] + wpart[i & 1][g][1])
                        + (wpart[i & 1][g][2] + wpart[i & 1][g][3]);
        scale = rsqrtf(tot);        // |v| in [0.8, 1.1]; eps guard never binds
        c += 1.0f;
        // wpart slot (i&1) is rewritten at step i+2, after the barrier of
        // step i+1 -> no WAR hazard.
    }

    // Emit new_anchors (scale applied) then new_counts.
#pragma unroll
    for (int j = 0; j < 2; ++j) {
        float4 v = A[j];
        v.x *= scale; v.y *= scale; v.z *= scale; v.w *= scale;
        reinterpret_cast<float4*>(out + BATCH)[(size_t)g * C4 + j * 128 + base] = v;
    }
    if ((t & 127) == 0) out[BATCH + KANCH * CH + g] = c;
}

// ---------------------------------------------------------------------------
extern "C" void kernel_launch(void* const* d_in, const int* in_sizes, int n_in,
                              void* d_out, int out_size) {
    const float* prompt_tokens = (const float*)d_in[0];  // [64,4096,1024] f32
    const float* anchors       = (const float*)d_in[1];  // [8,1024] f32
    const float* counts        = (const float*)d_in[2];  // [8] f32
    float* out = (float*)d_out;  // [64 ids | 8192 anchors | 8 counts] f32

    dim3 grid1(NSPLIT, BATCH);
    k_main<<<grid1, 256>>>(prompt_tokens, anchors, out);
    k_ema4<<<1, 1024>>>(anchors, counts, out);
}